// round 7
// baseline (speedup 1.0000x reference)
#include <cuda_runtime.h>
#include <cuda_fp16.h>

#define N_ATOMS 50000
#define N_PAIRS 800000
#define FDIM    128
#define F3      384

// ---------------- scratch (device globals; no runtime allocation) ----------
__device__ int    g_count [N_ATOMS];
__device__ int    g_cursor[N_ATOMS];
__device__ int    g_offset[N_ATOMS + 1];
__device__ int    g_pairidx[N_PAIRS];
__device__ float  g_h  [(size_t)N_ATOMS * FDIM];  // 25.6 MB
__device__ __half g_xh [(size_t)N_ATOMS * F3];    // 38.4 MB (x in fp16)
__device__ __half g_muh[(size_t)N_ATOMS * F3];    // 38.4 MB (mu in fp16)

// ---------------- small float4 helpers -------------------------------------
__device__ __forceinline__ float4 f4add(float4 a, float4 b) {
    return make_float4(a.x + b.x, a.y + b.y, a.z + b.z, a.w + b.w);
}
__device__ __forceinline__ float4 f4mul(float4 a, float4 b) {
    return make_float4(a.x * b.x, a.y * b.y, a.z * b.z, a.w * b.w);
}
__device__ __forceinline__ float4 f4fma(float4 a, float4 b, float4 c) {
    return make_float4(fmaf(a.x, b.x, c.x), fmaf(a.y, b.y, c.y),
                       fmaf(a.z, b.z, c.z), fmaf(a.w, b.w, c.w));
}
__device__ __forceinline__ float4 f4fmas(float4 a, float s, float4 c) {
    return make_float4(fmaf(a.x, s, c.x), fmaf(a.y, s, c.y),
                       fmaf(a.z, s, c.z), fmaf(a.w, s, c.w));
}
__device__ __forceinline__ float4 h4tof4(uint2 u) {
    __half2 a = *reinterpret_cast<__half2*>(&u.x);
    __half2 b = *reinterpret_cast<__half2*>(&u.y);
    float2 fa = __half22float2(a), fb = __half22float2(b);
    return make_float4(fa.x, fa.y, fb.x, fb.y);
}

// ---------------- cp.async helpers ------------------------------------------
__device__ __forceinline__ unsigned smem_u32(const void* p) {
    return (unsigned)__cvta_generic_to_shared(p);
}
__device__ __forceinline__ void cp16(unsigned d, const void* s) {
    asm volatile("cp.async.cg.shared.global [%0], [%1], 16;" :: "r"(d), "l"(s));
}
__device__ __forceinline__ void cp8(unsigned d, const void* s) {
    asm volatile("cp.async.ca.shared.global [%0], [%1], 8;" :: "r"(d), "l"(s));
}
__device__ __forceinline__ void cp_commit() {
    asm volatile("cp.async.commit_group;");
}
template<int N> __device__ __forceinline__ void cp_wait() {
    asm volatile("cp.async.wait_group %0;" :: "n"(N));
}

// ---------------- CSR build -------------------------------------------------
__global__ void k_zero() {
    int i = blockIdx.x * blockDim.x + threadIdx.x;
    if (i < N_ATOMS) { g_count[i] = 0; g_cursor[i] = 0; }
}

__global__ void k_hist(const int* __restrict__ idx_i) {
    int p = blockIdx.x * blockDim.x + threadIdx.x;
    if (p < N_PAIRS) atomicAdd(&g_count[idx_i[p]], 1);
}

__global__ void k_scan() {
    __shared__ int warpsum[33];
    int lane = threadIdx.x & 31, wid = threadIdx.x >> 5;
    int running = 0;
    for (int base = 0; base < N_ATOMS; base += 1024) {
        int idx = base + (int)threadIdx.x;
        int v = (idx < N_ATOMS) ? g_count[idx] : 0;
        int incl = v;
        #pragma unroll
        for (int off = 1; off < 32; off <<= 1) {
            int t = __shfl_up_sync(0xffffffff, incl, off);
            if (lane >= off) incl += t;
        }
        if (lane == 31) warpsum[wid] = incl;
        __syncthreads();
        if (wid == 0) {
            int s = warpsum[lane];
            int si = s;
            #pragma unroll
            for (int off = 1; off < 32; off <<= 1) {
                int t = __shfl_up_sync(0xffffffff, si, off);
                if (lane >= off) si += t;
            }
            warpsum[lane] = si - s;
            if (lane == 31) warpsum[32] = si;
        }
        __syncthreads();
        if (idx < N_ATOMS) g_offset[idx] = running + warpsum[wid] + incl - v;
        running += warpsum[32];
        __syncthreads();
    }
    if (threadIdx.x == 0) g_offset[N_ATOMS] = running;
}

__global__ void k_scatter(const int* __restrict__ idx_i) {
    int p = blockIdx.x * blockDim.x + threadIdx.x;
    if (p < N_PAIRS) {
        int i = idx_i[p];
        int pos = atomicAdd(&g_cursor[i], 1);
        g_pairidx[g_offset[i] + pos] = p;
    }
}

// ---------------- mu -> fp16 mirror ----------------------------------------
__global__ void k_cvt_mu(const float* __restrict__ mu) {
    size_t i = (size_t)blockIdx.x * blockDim.x + threadIdx.x;
    size_t n4 = (size_t)N_ATOMS * F3 / 4;
    if (i >= n4) return;
    float4 v = reinterpret_cast<const float4*>(mu)[i];
    __half2 h0 = __floats2half2_rn(v.x, v.y);
    __half2 h1 = __floats2half2_rn(v.z, v.w);
    uint2 u;
    u.x = *reinterpret_cast<unsigned*>(&h0);
    u.y = *reinterpret_cast<unsigned*>(&h1);
    reinterpret_cast<uint2*>(g_muh)[i] = u;
}

// ---------------- 2xTF32 tensor-core GEMM ----------------------------------
__device__ __forceinline__ unsigned cvt_tf32(float x) {
    unsigned r; asm("cvt.rna.tf32.f32 %0, %1;" : "=r"(r) : "f"(x)); return r;
}
__device__ __forceinline__ void mma_tf32(float* d, const unsigned* a, const unsigned* b) {
    asm volatile(
        "mma.sync.aligned.m16n8k8.row.col.f32.tf32.tf32.f32 "
        "{%0,%1,%2,%3}, {%4,%5,%6,%7}, {%8,%9}, {%0,%1,%2,%3};"
        : "+f"(d[0]), "+f"(d[1]), "+f"(d[2]), "+f"(d[3])
        : "r"(a[0]), "r"(a[1]), "r"(a[2]), "r"(a[3]), "r"(b[0]), "r"(b[1]));
}

#define GBM 128
#define GBN 64
#define GBK 16
#define SROW 20

template<bool OUT_HALF, bool DO_SILU>
__global__ __launch_bounds__(256)
void gemm_tc(const float* __restrict__ A, const float* __restrict__ W,
             const float* __restrict__ bias, void* __restrict__ outv,
             int M, int N) {
    __shared__ float As[GBM * SROW];
    __shared__ float Ws[GBN * SROW];

    int tid  = threadIdx.x;
    int warp = tid >> 5, lane = tid & 31;
    int g = lane >> 2, t4 = lane & 3;
    int wm = warp >> 1, wn = warp & 1;
    int bm = blockIdx.y * GBM, bn = blockIdx.x * GBN;

    float acc[2][4][4];
    #pragma unroll
    for (int i = 0; i < 2; i++)
        #pragma unroll
        for (int j = 0; j < 4; j++)
            #pragma unroll
            for (int k = 0; k < 4; k++) acc[i][j][k] = 0.f;

    for (int k0 = 0; k0 < 128; k0 += GBK) {
        #pragma unroll
        for (int r = 0; r < 2; r++) {
            int t  = tid + r * 256;
            int ml = t >> 2, kq = (t & 3) * 4;
            int m = bm + ml;
            float4 v = make_float4(0, 0, 0, 0);
            if (m < M) v = *reinterpret_cast<const float4*>(A + (size_t)m * 128 + k0 + kq);
            *reinterpret_cast<float4*>(As + ml * SROW + kq) = v;
        }
        {
            int nl = tid >> 2, kq = (tid & 3) * 4;
            float4 v = *reinterpret_cast<const float4*>(W + (size_t)(bn + nl) * 128 + k0 + kq);
            *reinterpret_cast<float4*>(Ws + nl * SROW + kq) = v;
        }
        __syncthreads();

        #pragma unroll
        for (int ks = 0; ks < 2; ks++) {
            int kb = ks * 8;
            unsigned ah[2][4], al[2][4], bh[4][2];
            #pragma unroll
            for (int tm = 0; tm < 2; tm++) {
                int mb = wm * 32 + tm * 16;
                float f0 = As[(mb + g)     * SROW + kb + t4];
                float f1 = As[(mb + 8 + g) * SROW + kb + t4];
                float f2 = As[(mb + g)     * SROW + kb + t4 + 4];
                float f3 = As[(mb + 8 + g) * SROW + kb + t4 + 4];
                ah[tm][0] = cvt_tf32(f0); al[tm][0] = cvt_tf32(f0 - __uint_as_float(ah[tm][0]));
                ah[tm][1] = cvt_tf32(f1); al[tm][1] = cvt_tf32(f1 - __uint_as_float(ah[tm][1]));
                ah[tm][2] = cvt_tf32(f2); al[tm][2] = cvt_tf32(f2 - __uint_as_float(ah[tm][2]));
                ah[tm][3] = cvt_tf32(f3); al[tm][3] = cvt_tf32(f3 - __uint_as_float(ah[tm][3]));
            }
            #pragma unroll
            for (int tn = 0; tn < 4; tn++) {
                int nb = wn * 32 + tn * 8;
                bh[tn][0] = cvt_tf32(Ws[(nb + g) * SROW + kb + t4]);
                bh[tn][1] = cvt_tf32(Ws[(nb + g) * SROW + kb + t4 + 4]);
            }
            #pragma unroll
            for (int tm = 0; tm < 2; tm++)
                #pragma unroll
                for (int tn = 0; tn < 4; tn++) {
                    mma_tf32(acc[tm][tn], ah[tm], bh[tn]);
                    mma_tf32(acc[tm][tn], al[tm], bh[tn]);
                }
        }
        __syncthreads();
    }

    #pragma unroll
    for (int tm = 0; tm < 2; tm++) {
        #pragma unroll
        for (int tn = 0; tn < 4; tn++) {
            int row0 = bm + wm * 32 + tm * 16 + g;
            int col  = bn + wn * 32 + tn * 8 + t4 * 2;
            float b0 = __ldg(bias + col), b1 = __ldg(bias + col + 1);
            float v0 = acc[tm][tn][0] + b0;
            float v1 = acc[tm][tn][1] + b1;
            float v2 = acc[tm][tn][2] + b0;
            float v3 = acc[tm][tn][3] + b1;
            if (DO_SILU) {
                v0 = v0 / (1.0f + __expf(-v0));
                v1 = v1 / (1.0f + __expf(-v1));
                v2 = v2 / (1.0f + __expf(-v2));
                v3 = v3 / (1.0f + __expf(-v3));
            }
            if (OUT_HALF) {
                __half* outh = (__half*)outv;
                __half2 h01 = __floats2half2_rn(v0, v1);
                __half2 h23 = __floats2half2_rn(v2, v3);
                if (row0 < M)
                    *reinterpret_cast<__half2*>(outh + (size_t)row0 * N + col) = h01;
                if (row0 + 8 < M)
                    *reinterpret_cast<__half2*>(outh + (size_t)(row0 + 8) * N + col) = h23;
            } else {
                float* outf = (float*)outv;
                if (row0 < M)
                    *reinterpret_cast<float2*>(outf + (size_t)row0 * N + col) = make_float2(v0, v1);
                if (row0 + 8 < M)
                    *reinterpret_cast<float2*>(outf + (size_t)(row0 + 8) * N + col) = make_float2(v2, v3);
            }
        }
    }
}

// ---------------- aggregation: cp.async staged pipeline ---------------------
// Per-warp smem ring, DEPTH stages. Each lane copies exactly the bytes it
// later reads -> per-thread wait_group is sufficient (no per-pair syncwarp).
#define ADEPTH 4
#define MAXSEG 64

// dynamic smem layout (per block, 4 warps):
//   sw  : 4 * ADEPTH*96 float4  = 24576 B   (Wij stage)
//   sx  : 4 * ADEPTH*96 uint2   = 12288 B   (x half stage)
//   sm  : 4 * ADEPTH*96 uint2   = 12288 B   (mu half stage)
//   sp  : 4 * MAXSEG int        =  1024 B   (pair idx cache)
//   sj  : 4 * MAXSEG int        =  1024 B   (j idx cache)
//   sd  : 4 * MAXSEG float4     =  4096 B   (dir cache)
// total = 55296 B
#define AGG_SMEM 55296

__global__ __launch_bounds__(128)
void k_agg(const float* __restrict__ q, const float* __restrict__ mu,
           const float* __restrict__ Wij, const float* __restrict__ dir,
           const int* __restrict__ idxj, float* __restrict__ out) {
    extern __shared__ char dsm[];
    int warp = threadIdx.x >> 5;
    int lane = threadIdx.x & 31;

    float4* sw = reinterpret_cast<float4*>(dsm)                  + warp * (ADEPTH * 96);
    uint2*  sx = reinterpret_cast<uint2*>(dsm + 24576)           + warp * (ADEPTH * 96);
    uint2*  sm = reinterpret_cast<uint2*>(dsm + 24576 + 12288)   + warp * (ADEPTH * 96);
    int*    sp = reinterpret_cast<int*>(dsm + 49152)             + warp * MAXSEG;
    int*    sj = reinterpret_cast<int*>(dsm + 49152 + 1024)      + warp * MAXSEG;
    float4* sd = reinterpret_cast<float4*>(dsm + 49152 + 2048)   + warp * MAXSEG;

    int i = blockIdx.x * 4 + warp;
    if (i >= N_ATOMS) return;

    int s = g_offset[i], e = g_offset[i + 1];
    int n = e - s;

    // stage the segment's index/dir stream once
    int nc = n < MAXSEG ? n : MAXSEG;
    for (int t = lane; t < nc; t += 32) {
        int p = __ldg(g_pairidx + s + t);
        sp[t] = p;
        sj[t] = __ldg(idxj + p);
        sd[t] = make_float4(__ldg(dir + (size_t)p * 3 + 0),
                            __ldg(dir + (size_t)p * 3 + 1),
                            __ldg(dir + (size_t)p * 3 + 2), 0.f);
    }
    __syncwarp();

    float4 aq = make_float4(0, 0, 0, 0);
    float4 a0 = aq, a1 = aq, a2 = aq;

    // issue stage t into ring slot t&3 (always commits a group, even if empty)
    auto issue = [&](int t) {
        if (t < n) {
            int p, j;
            if (t < MAXSEG) { p = sp[t]; j = sj[t]; }
            else { p = __ldg(g_pairidx + s + t); j = __ldg(idxj + p); }
            int slot = t & (ADEPTH - 1);
            const char* wsrc = (const char*)Wij   + (size_t)p * 1536 + lane * 16;
            const char* xsrc = (const char*)g_xh  + (size_t)j * 768  + lane * 8;
            const char* msrc = (const char*)g_muh + (size_t)j * 768  + lane * 8;
            unsigned wdst = smem_u32(sw + slot * 96 + lane);
            unsigned xdst = smem_u32(sx + slot * 96 + lane);
            unsigned mdst = smem_u32(sm + slot * 96 + lane);
            cp16(wdst,        wsrc);
            cp16(wdst + 512,  wsrc + 512);
            cp16(wdst + 1024, wsrc + 1024);
            cp8(xdst,       xsrc);
            cp8(xdst + 256, xsrc + 256);
            cp8(xdst + 512, xsrc + 512);
            cp8(mdst,       msrc);
            cp8(mdst + 256, msrc + 256);
            cp8(mdst + 512, msrc + 512);
        }
        cp_commit();
    };

    // prologue: ADEPTH-1 stages in flight
    issue(0); issue(1); issue(2);

    for (int t = 0; t < n; ++t) {
        issue(t + ADEPTH - 1);
        cp_wait<ADEPTH - 1>();          // stage t is now complete (this lane)

        int slot = t & (ADEPTH - 1);
        float4 w0 = sw[slot * 96 + lane];
        float4 w1 = sw[slot * 96 + lane + 32];
        float4 w2 = sw[slot * 96 + lane + 64];
        float4 x0 = h4tof4(sx[slot * 96 + lane]);
        float4 x1 = h4tof4(sx[slot * 96 + lane + 32]);
        float4 x2 = h4tof4(sx[slot * 96 + lane + 64]);
        float4 m0 = h4tof4(sm[slot * 96 + lane]);
        float4 m1 = h4tof4(sm[slot * 96 + lane + 32]);
        float4 m2 = h4tof4(sm[slot * 96 + lane + 64]);

        float4 dv;
        if (t < MAXSEG) dv = sd[t];
        else {
            int p = __ldg(g_pairidx + s + t);
            dv = make_float4(__ldg(dir + (size_t)p * 3 + 0),
                             __ldg(dir + (size_t)p * 3 + 1),
                             __ldg(dir + (size_t)p * 3 + 2), 0.f);
        }

        aq = f4fma(w0, x0, aq);
        float4 R  = f4mul(w1, x1);
        float4 MM = f4mul(w2, x2);
        a0 = f4fma(MM, m0, f4fmas(R, dv.x, a0));
        a1 = f4fma(MM, m1, f4fmas(R, dv.y, a1));
        a2 = f4fma(MM, m2, f4fmas(R, dv.z, a2));
    }

    const float4* qp = reinterpret_cast<const float4*>(q) + (size_t)i * 32;
    float4* oq = reinterpret_cast<float4*>(out) + (size_t)i * 32;
    oq[lane] = f4add(qp[lane], aq);

    const float4* mup = reinterpret_cast<const float4*>(mu) + (size_t)i * 96;
    float4* om = reinterpret_cast<float4*>(out + (size_t)N_ATOMS * FDIM) + (size_t)i * 96;
    om[lane]      = f4add(mup[lane],      a0);
    om[lane + 32] = f4add(mup[lane + 32], a1);
    om[lane + 64] = f4add(mup[lane + 64], a2);
}

// ---------------- launch ----------------------------------------------------
static cudaStream_t s_side = nullptr;
static cudaEvent_t  s_evFork = nullptr, s_evJoin = nullptr;

extern "C" void kernel_launch(void* const* d_in, const int* in_sizes, int n_in,
                              void* d_out, int out_size) {
    const float* q   = (const float*)d_in[0];
    const float* mu  = (const float*)d_in[1];
    const float* Wij = (const float*)d_in[2];
    const float* dir = (const float*)d_in[3];
    const int*   pl  = (const int*)d_in[4];
    const float* W1  = (const float*)d_in[5];
    const float* b1  = (const float*)d_in[6];
    const float* W2  = (const float*)d_in[7];
    const float* b2  = (const float*)d_in[8];
    float* out = (float*)d_out;

    const int* idx_i = pl;
    const int* idx_j = pl + N_PAIRS;

    float  *hbuf = nullptr;
    __half *xh   = nullptr;
    cudaGetSymbolAddress((void**)&hbuf, g_h);
    cudaGetSymbolAddress((void**)&xh,   g_xh);

    if (!s_side) {
        cudaStreamCreateWithFlags(&s_side, cudaStreamNonBlocking);
        cudaEventCreateWithFlags(&s_evFork, cudaEventDisableTiming);
        cudaEventCreateWithFlags(&s_evJoin, cudaEventDisableTiming);
        cudaFuncSetAttribute(k_agg, cudaFuncAttributeMaxDynamicSharedMemorySize, AGG_SMEM);
    }

    // fork: CSR chain + mu conversion on side stream, GEMM chain on main
    cudaEventRecord(s_evFork, 0);
    cudaStreamWaitEvent(s_side, s_evFork, 0);

    k_zero   <<<(N_ATOMS + 255) / 256, 256, 0, s_side>>>();
    k_hist   <<<(N_PAIRS + 255) / 256, 256, 0, s_side>>>(idx_i);
    k_scan   <<<1, 1024, 0, s_side>>>();
    k_scatter<<<(N_PAIRS + 255) / 256, 256, 0, s_side>>>(idx_i);
    {
        size_t n4 = (size_t)N_ATOMS * F3 / 4;
        k_cvt_mu<<<(unsigned)((n4 + 255) / 256), 256, 0, s_side>>>(mu);
    }
    cudaEventRecord(s_evJoin, s_side);

    dim3 g1(FDIM / GBN, (N_ATOMS + GBM - 1) / GBM);
    gemm_tc<false, true><<<g1, 256>>>(q, W1, b1, hbuf, N_ATOMS, FDIM);
    dim3 g2(F3 / GBN, (N_ATOMS + GBM - 1) / GBM);
    gemm_tc<true, false><<<g2, 256>>>(hbuf, W2, b2, xh, N_ATOMS, F3);

    // join, then aggregate
    cudaStreamWaitEvent(0, s_evJoin, 0);
    k_agg<<<(N_ATOMS + 3) / 4, 128, AGG_SMEM>>>(q, mu, Wij, dir, idx_j, out);
}

// round 8
// speedup vs baseline: 1.0420x; 1.0420x over previous
#include <cuda_runtime.h>
#include <cuda_fp16.h>

#define N_ATOMS 50000
#define N_PAIRS 800000
#define FDIM    128
#define F3      384

// ---------------- scratch (device globals; no runtime allocation) ----------
__device__ int    g_count [N_ATOMS];
__device__ int    g_cursor[N_ATOMS];
__device__ int    g_offset[N_ATOMS + 1];
__device__ int    g_pairidx[N_PAIRS];
__device__ float  g_h  [(size_t)N_ATOMS * FDIM];  // 25.6 MB
__device__ __half g_xh [(size_t)N_ATOMS * F3];    // 38.4 MB (x in fp16)
__device__ __half g_muh[(size_t)N_ATOMS * F3];    // 38.4 MB (mu in fp16)

// ---------------- small float4 helpers -------------------------------------
__device__ __forceinline__ float4 f4add(float4 a, float4 b) {
    return make_float4(a.x + b.x, a.y + b.y, a.z + b.z, a.w + b.w);
}
__device__ __forceinline__ float4 f4mul(float4 a, float4 b) {
    return make_float4(a.x * b.x, a.y * b.y, a.z * b.z, a.w * b.w);
}
__device__ __forceinline__ float4 f4fma(float4 a, float4 b, float4 c) {
    return make_float4(fmaf(a.x, b.x, c.x), fmaf(a.y, b.y, c.y),
                       fmaf(a.z, b.z, c.z), fmaf(a.w, b.w, c.w));
}
__device__ __forceinline__ float4 f4fmas(float4 a, float s, float4 c) {
    return make_float4(fmaf(a.x, s, c.x), fmaf(a.y, s, c.y),
                       fmaf(a.z, s, c.z), fmaf(a.w, s, c.w));
}
__device__ __forceinline__ float4 h4tof4(uint2 u) {
    __half2 a = *reinterpret_cast<__half2*>(&u.x);
    __half2 b = *reinterpret_cast<__half2*>(&u.y);
    float2 fa = __half22float2(a), fb = __half22float2(b);
    return make_float4(fa.x, fa.y, fb.x, fb.y);
}

// ---------------- cp.async helpers ------------------------------------------
__device__ __forceinline__ unsigned smem_u32(const void* p) {
    return (unsigned)__cvta_generic_to_shared(p);
}
__device__ __forceinline__ void cp16(unsigned d, const void* s) {
    asm volatile("cp.async.cg.shared.global [%0], [%1], 16;" :: "r"(d), "l"(s));
}
__device__ __forceinline__ void cp_commit() {
    asm volatile("cp.async.commit_group;");
}
template<int N> __device__ __forceinline__ void cp_wait() {
    asm volatile("cp.async.wait_group %0;" :: "n"(N));
}

// ---------------- CSR build -------------------------------------------------
__global__ void k_zero() {
    int i = blockIdx.x * blockDim.x + threadIdx.x;
    if (i < N_ATOMS) { g_count[i] = 0; g_cursor[i] = 0; }
}

__global__ void k_hist(const int* __restrict__ idx_i) {
    int p = blockIdx.x * blockDim.x + threadIdx.x;
    if (p < N_PAIRS) atomicAdd(&g_count[idx_i[p]], 1);
}

__global__ void k_scan() {
    __shared__ int warpsum[33];
    int lane = threadIdx.x & 31, wid = threadIdx.x >> 5;
    int running = 0;
    for (int base = 0; base < N_ATOMS; base += 1024) {
        int idx = base + (int)threadIdx.x;
        int v = (idx < N_ATOMS) ? g_count[idx] : 0;
        int incl = v;
        #pragma unroll
        for (int off = 1; off < 32; off <<= 1) {
            int t = __shfl_up_sync(0xffffffff, incl, off);
            if (lane >= off) incl += t;
        }
        if (lane == 31) warpsum[wid] = incl;
        __syncthreads();
        if (wid == 0) {
            int s = warpsum[lane];
            int si = s;
            #pragma unroll
            for (int off = 1; off < 32; off <<= 1) {
                int t = __shfl_up_sync(0xffffffff, si, off);
                if (lane >= off) si += t;
            }
            warpsum[lane] = si - s;
            if (lane == 31) warpsum[32] = si;
        }
        __syncthreads();
        if (idx < N_ATOMS) g_offset[idx] = running + warpsum[wid] + incl - v;
        running += warpsum[32];
        __syncthreads();
    }
    if (threadIdx.x == 0) g_offset[N_ATOMS] = running;
}

__global__ void k_scatter(const int* __restrict__ idx_i) {
    int p = blockIdx.x * blockDim.x + threadIdx.x;
    if (p < N_PAIRS) {
        int i = idx_i[p];
        int pos = atomicAdd(&g_cursor[i], 1);
        g_pairidx[g_offset[i] + pos] = p;
    }
}

// ---------------- mu -> fp16 mirror ----------------------------------------
__global__ void k_cvt_mu(const float* __restrict__ mu) {
    size_t i = (size_t)blockIdx.x * blockDim.x + threadIdx.x;
    size_t n4 = (size_t)N_ATOMS * F3 / 4;
    if (i >= n4) return;
    float4 v = reinterpret_cast<const float4*>(mu)[i];
    __half2 h0 = __floats2half2_rn(v.x, v.y);
    __half2 h1 = __floats2half2_rn(v.z, v.w);
    uint2 u;
    u.x = *reinterpret_cast<unsigned*>(&h0);
    u.y = *reinterpret_cast<unsigned*>(&h1);
    reinterpret_cast<uint2*>(g_muh)[i] = u;
}

// ---------------- 2xTF32 tensor-core GEMM ----------------------------------
__device__ __forceinline__ unsigned cvt_tf32(float x) {
    unsigned r; asm("cvt.rna.tf32.f32 %0, %1;" : "=r"(r) : "f"(x)); return r;
}
__device__ __forceinline__ void mma_tf32(float* d, const unsigned* a, const unsigned* b) {
    asm volatile(
        "mma.sync.aligned.m16n8k8.row.col.f32.tf32.tf32.f32 "
        "{%0,%1,%2,%3}, {%4,%5,%6,%7}, {%8,%9}, {%0,%1,%2,%3};"
        : "+f"(d[0]), "+f"(d[1]), "+f"(d[2]), "+f"(d[3])
        : "r"(a[0]), "r"(a[1]), "r"(a[2]), "r"(a[3]), "r"(b[0]), "r"(b[1]));
}

#define GBM 128
#define GBN 64
#define GBK 16
#define SROW 20

template<bool OUT_HALF, bool DO_SILU>
__global__ __launch_bounds__(256)
void gemm_tc(const float* __restrict__ A, const float* __restrict__ W,
             const float* __restrict__ bias, void* __restrict__ outv,
             int M, int N) {
    __shared__ float As[GBM * SROW];
    __shared__ float Ws[GBN * SROW];

    int tid  = threadIdx.x;
    int warp = tid >> 5, lane = tid & 31;
    int g = lane >> 2, t4 = lane & 3;
    int wm = warp >> 1, wn = warp & 1;
    int bm = blockIdx.y * GBM, bn = blockIdx.x * GBN;

    float acc[2][4][4];
    #pragma unroll
    for (int i = 0; i < 2; i++)
        #pragma unroll
        for (int j = 0; j < 4; j++)
            #pragma unroll
            for (int k = 0; k < 4; k++) acc[i][j][k] = 0.f;

    for (int k0 = 0; k0 < 128; k0 += GBK) {
        #pragma unroll
        for (int r = 0; r < 2; r++) {
            int t  = tid + r * 256;
            int ml = t >> 2, kq = (t & 3) * 4;
            int m = bm + ml;
            float4 v = make_float4(0, 0, 0, 0);
            if (m < M) v = *reinterpret_cast<const float4*>(A + (size_t)m * 128 + k0 + kq);
            *reinterpret_cast<float4*>(As + ml * SROW + kq) = v;
        }
        {
            int nl = tid >> 2, kq = (tid & 3) * 4;
            float4 v = *reinterpret_cast<const float4*>(W + (size_t)(bn + nl) * 128 + k0 + kq);
            *reinterpret_cast<float4*>(Ws + nl * SROW + kq) = v;
        }
        __syncthreads();

        #pragma unroll
        for (int ks = 0; ks < 2; ks++) {
            int kb = ks * 8;
            unsigned ah[2][4], al[2][4], bh[4][2];
            #pragma unroll
            for (int tm = 0; tm < 2; tm++) {
                int mb = wm * 32 + tm * 16;
                float f0 = As[(mb + g)     * SROW + kb + t4];
                float f1 = As[(mb + 8 + g) * SROW + kb + t4];
                float f2 = As[(mb + g)     * SROW + kb + t4 + 4];
                float f3 = As[(mb + 8 + g) * SROW + kb + t4 + 4];
                ah[tm][0] = cvt_tf32(f0); al[tm][0] = cvt_tf32(f0 - __uint_as_float(ah[tm][0]));
                ah[tm][1] = cvt_tf32(f1); al[tm][1] = cvt_tf32(f1 - __uint_as_float(ah[tm][1]));
                ah[tm][2] = cvt_tf32(f2); al[tm][2] = cvt_tf32(f2 - __uint_as_float(ah[tm][2]));
                ah[tm][3] = cvt_tf32(f3); al[tm][3] = cvt_tf32(f3 - __uint_as_float(ah[tm][3]));
            }
            #pragma unroll
            for (int tn = 0; tn < 4; tn++) {
                int nb = wn * 32 + tn * 8;
                bh[tn][0] = cvt_tf32(Ws[(nb + g) * SROW + kb + t4]);
                bh[tn][1] = cvt_tf32(Ws[(nb + g) * SROW + kb + t4 + 4]);
            }
            #pragma unroll
            for (int tm = 0; tm < 2; tm++)
                #pragma unroll
                for (int tn = 0; tn < 4; tn++) {
                    mma_tf32(acc[tm][tn], ah[tm], bh[tn]);
                    mma_tf32(acc[tm][tn], al[tm], bh[tn]);
                }
        }
        __syncthreads();
    }

    #pragma unroll
    for (int tm = 0; tm < 2; tm++) {
        #pragma unroll
        for (int tn = 0; tn < 4; tn++) {
            int row0 = bm + wm * 32 + tm * 16 + g;
            int col  = bn + wn * 32 + tn * 8 + t4 * 2;
            float b0 = __ldg(bias + col), b1 = __ldg(bias + col + 1);
            float v0 = acc[tm][tn][0] + b0;
            float v1 = acc[tm][tn][1] + b1;
            float v2 = acc[tm][tn][2] + b0;
            float v3 = acc[tm][tn][3] + b1;
            if (DO_SILU) {
                v0 = v0 / (1.0f + __expf(-v0));
                v1 = v1 / (1.0f + __expf(-v1));
                v2 = v2 / (1.0f + __expf(-v2));
                v3 = v3 / (1.0f + __expf(-v3));
            }
            if (OUT_HALF) {
                __half* outh = (__half*)outv;
                __half2 h01 = __floats2half2_rn(v0, v1);
                __half2 h23 = __floats2half2_rn(v2, v3);
                if (row0 < M)
                    *reinterpret_cast<__half2*>(outh + (size_t)row0 * N + col) = h01;
                if (row0 + 8 < M)
                    *reinterpret_cast<__half2*>(outh + (size_t)(row0 + 8) * N + col) = h23;
            } else {
                float* outf = (float*)outv;
                if (row0 < M)
                    *reinterpret_cast<float2*>(outf + (size_t)row0 * N + col) = make_float2(v0, v1);
                if (row0 + 8 < M)
                    *reinterpret_cast<float2*>(outf + (size_t)(row0 + 8) * N + col) = make_float2(v2, v3);
            }
        }
    }
}

// ---------------- aggregation: asymmetric pipeline ---------------------------
// Wij (always DRAM) -> cp.async ring depth 4 in smem.
// x/mu (mostly L2)  -> register ping-pong depth 2.
#define WDEPTH 4
#define MAXSEG 64

// dynamic smem per block (4 warps):
//   sw : 4 warps * WDEPTH*96 float4 = 24576 B  (Wij ring)
//   sp : 4 * MAXSEG int             =  1024 B
//   sj : 4 * MAXSEG int             =  1024 B
//   sd : 4 * MAXSEG float4          =  4096 B
#define AGG_SMEM (24576 + 1024 + 1024 + 4096)

struct XM {               // x/mu register stage: 15 regs
    uint2 x0, x1, x2, m0, m1, m2;
    float d0, d1, d2;
};

__global__ __launch_bounds__(128)
void k_agg(const float* __restrict__ q, const float* __restrict__ mu,
           const float* __restrict__ Wij, const float* __restrict__ dir,
           const int* __restrict__ idxj, float* __restrict__ out) {
    extern __shared__ char dsm[];
    int warp = threadIdx.x >> 5;
    int lane = threadIdx.x & 31;

    float4* sw = reinterpret_cast<float4*>(dsm)              + warp * (WDEPTH * 96);
    int*    sp = reinterpret_cast<int*>(dsm + 24576)         + warp * MAXSEG;
    int*    sj = reinterpret_cast<int*>(dsm + 24576 + 1024)  + warp * MAXSEG;
    float4* sd = reinterpret_cast<float4*>(dsm + 24576 + 2048) + warp * MAXSEG;

    int i = blockIdx.x * 4 + warp;
    if (i >= N_ATOMS) return;

    int s = g_offset[i], e = g_offset[i + 1];
    int n = e - s;

    // stage index/dir stream (first MAXSEG entries)
    int nc = n < MAXSEG ? n : MAXSEG;
    for (int t = lane; t < nc; t += 32) {
        int p = __ldg(g_pairidx + s + t);
        sp[t] = p;
        sj[t] = __ldg(idxj + p);
        sd[t] = make_float4(__ldg(dir + (size_t)p * 3 + 0),
                            __ldg(dir + (size_t)p * 3 + 1),
                            __ldg(dir + (size_t)p * 3 + 2), 0.f);
    }
    __syncwarp();

    float4 aq = make_float4(0, 0, 0, 0);
    float4 a0 = aq, a1 = aq, a2 = aq;

    // Wij issue (cp.async, always commits a group)
    auto issue_w = [&](int t) {
        if (t < n) {
            int p = (t < MAXSEG) ? sp[t] : __ldg(g_pairidx + s + t);
            int slot = t & (WDEPTH - 1);
            const char* wsrc = (const char*)Wij + (size_t)p * 1536 + lane * 16;
            unsigned wdst = smem_u32(sw + slot * 96 + lane);
            cp16(wdst,        wsrc);
            cp16(wdst + 512,  wsrc + 512);
            cp16(wdst + 1024, wsrc + 1024);
        }
        cp_commit();
    };

    // x/mu register load
    auto load_xm = [&](XM& R, int t) {
        int p, j;
        if (t < MAXSEG) {
            j = sj[t];
            float4 dv = sd[t];
            R.d0 = dv.x; R.d1 = dv.y; R.d2 = dv.z;
        } else {
            p = __ldg(g_pairidx + s + t);
            j = __ldg(idxj + p);
            R.d0 = __ldg(dir + (size_t)p * 3 + 0);
            R.d1 = __ldg(dir + (size_t)p * 3 + 1);
            R.d2 = __ldg(dir + (size_t)p * 3 + 2);
        }
        const uint2* xp = reinterpret_cast<const uint2*>(g_xh)  + (size_t)j * 96;
        const uint2* mp = reinterpret_cast<const uint2*>(g_muh) + (size_t)j * 96;
        R.x0 = xp[lane]; R.x1 = xp[lane + 32]; R.x2 = xp[lane + 64];
        R.m0 = mp[lane]; R.m1 = mp[lane + 32]; R.m2 = mp[lane + 64];
    };

    auto accum = [&](const XM& R, int slot) {
        float4 w0 = sw[slot * 96 + lane];
        float4 w1 = sw[slot * 96 + lane + 32];
        float4 w2 = sw[slot * 96 + lane + 64];
        float4 x0 = h4tof4(R.x0), x1 = h4tof4(R.x1), x2 = h4tof4(R.x2);
        float4 m0 = h4tof4(R.m0), m1 = h4tof4(R.m1), m2 = h4tof4(R.m2);
        aq = f4fma(w0, x0, aq);
        float4 Rv = f4mul(w1, x1);
        float4 MM = f4mul(w2, x2);
        a0 = f4fma(MM, m0, f4fmas(Rv, R.d0, a0));
        a1 = f4fma(MM, m1, f4fmas(Rv, R.d1, a1));
        a2 = f4fma(MM, m2, f4fmas(Rv, R.d2, a2));
    };

    XM A, B;
    // prologue: 3 Wij stages in flight, x/mu stage 0 in registers
    issue_w(0); issue_w(1); issue_w(2);
    if (n > 0) load_xm(A, 0);

    for (int t = 0; t < n; ) {
        issue_w(t + 3);
        if (t + 1 < n) load_xm(B, t + 1);
        cp_wait<WDEPTH - 1>();                  // Wij stage t complete
        accum(A, t & (WDEPTH - 1));
        ++t;
        if (t >= n) break;

        issue_w(t + 3);
        if (t + 1 < n) load_xm(A, t + 1);
        cp_wait<WDEPTH - 1>();
        accum(B, t & (WDEPTH - 1));
        ++t;
    }

    const float4* qp = reinterpret_cast<const float4*>(q) + (size_t)i * 32;
    float4* oq = reinterpret_cast<float4*>(out) + (size_t)i * 32;
    oq[lane] = f4add(qp[lane], aq);

    const float4* mup = reinterpret_cast<const float4*>(mu) + (size_t)i * 96;
    float4* om = reinterpret_cast<float4*>(out + (size_t)N_ATOMS * FDIM) + (size_t)i * 96;
    om[lane]      = f4add(mup[lane],      a0);
    om[lane + 32] = f4add(mup[lane + 32], a1);
    om[lane + 64] = f4add(mup[lane + 64], a2);
}

// ---------------- launch ----------------------------------------------------
static cudaStream_t s_side = nullptr;
static cudaEvent_t  s_evFork = nullptr, s_evJoin = nullptr;

extern "C" void kernel_launch(void* const* d_in, const int* in_sizes, int n_in,
                              void* d_out, int out_size) {
    const float* q   = (const float*)d_in[0];
    const float* mu  = (const float*)d_in[1];
    const float* Wij = (const float*)d_in[2];
    const float* dir = (const float*)d_in[3];
    const int*   pl  = (const int*)d_in[4];
    const float* W1  = (const float*)d_in[5];
    const float* b1  = (const float*)d_in[6];
    const float* W2  = (const float*)d_in[7];
    const float* b2  = (const float*)d_in[8];
    float* out = (float*)d_out;

    const int* idx_i = pl;
    const int* idx_j = pl + N_PAIRS;

    float  *hbuf = nullptr;
    __half *xh   = nullptr;
    cudaGetSymbolAddress((void**)&hbuf, g_h);
    cudaGetSymbolAddress((void**)&xh,   g_xh);

    if (!s_side) {
        cudaStreamCreateWithFlags(&s_side, cudaStreamNonBlocking);
        cudaEventCreateWithFlags(&s_evFork, cudaEventDisableTiming);
        cudaEventCreateWithFlags(&s_evJoin, cudaEventDisableTiming);
        cudaFuncSetAttribute(k_agg, cudaFuncAttributeMaxDynamicSharedMemorySize, AGG_SMEM);
    }

    // fork: CSR chain + mu conversion on side stream, GEMM chain on main
    cudaEventRecord(s_evFork, 0);
    cudaStreamWaitEvent(s_side, s_evFork, 0);

    k_zero   <<<(N_ATOMS + 255) / 256, 256, 0, s_side>>>();
    k_hist   <<<(N_PAIRS + 255) / 256, 256, 0, s_side>>>(idx_i);
    k_scan   <<<1, 1024, 0, s_side>>>();
    k_scatter<<<(N_PAIRS + 255) / 256, 256, 0, s_side>>>(idx_i);
    {
        size_t n4 = (size_t)N_ATOMS * F3 / 4;
        k_cvt_mu<<<(unsigned)((n4 + 255) / 256), 256, 0, s_side>>>(mu);
    }
    cudaEventRecord(s_evJoin, s_side);

    dim3 g1(FDIM / GBN, (N_ATOMS + GBM - 1) / GBM);
    gemm_tc<false, true><<<g1, 256>>>(q, W1, b1, hbuf, N_ATOMS, FDIM);
    dim3 g2(F3 / GBN, (N_ATOMS + GBM - 1) / GBM);
    gemm_tc<true, false><<<g2, 256>>>(hbuf, W2, b2, xh, N_ATOMS, F3);

    // join, then aggregate
    cudaStreamWaitEvent(0, s_evJoin, 0);
    k_agg<<<(N_ATOMS + 3) / 4, 128, AGG_SMEM>>>(q, mu, Wij, dir, idx_j, out);
}